// round 15
// baseline (speedup 1.0000x reference)
#include <cuda_runtime.h>
#include <math.h>

#define NODES 20000

typedef unsigned long long ull;

__device__ float g_qkt[(size_t)NODES * 512];
__device__ float g_u[(size_t)NODES * 512];
__device__ float g_wkt[128 * 128];   // WkT[c][g] = Wk[g][c]

__device__ __forceinline__ ull pk2(float x) {
    unsigned xi = __float_as_uint(x);
    ull r;
    asm("mov.b64 %0, {%1, %1};" : "=l"(r) : "r"(xi), "r"(xi));
    return r;
}
__device__ __forceinline__ ull ffma2(ull a, ull b, ull c) {
    ull d;
    asm("fma.rn.f32x2 %0, %1, %2, %3;" : "=l"(d) : "l"(a), "l"(b), "l"(c));
    return d;
}
__device__ __forceinline__ void upk(ull v, float& lo, float& hi) {
    unsigned a, b;
    asm("mov.b64 {%0, %1}, %2;" : "=r"(a), "=r"(b) : "l"(v));
    lo = __uint_as_float(a); hi = __uint_as_float(b);
}

// 8 rows x 4 cols over 4 k: A from smem (warp-private rows, broadcast reads),
// B via 16B-per-lane loads from gB (global, coalesced 512B rows, L1-hot).
#define GEMM_STEP_LDGB(bA, kbase, gB, kg, c0, acc)                                     \
    {                                                                                   \
        ulonglong2 b0 = *(const ulonglong2*)((gB) + ((kg) + 0) * 128 + (c0));           \
        ulonglong2 b1 = *(const ulonglong2*)((gB) + ((kg) + 1) * 128 + (c0));           \
        ulonglong2 b2 = *(const ulonglong2*)((gB) + ((kg) + 2) * 128 + (c0));           \
        ulonglong2 b3 = *(const ulonglong2*)((gB) + ((kg) + 3) * 128 + (c0));           \
        _Pragma("unroll")                                                               \
        for (int i = 0; i < 8; i++) {                                                   \
            float4 a = *(const float4*)((bA) + i * 132 + (kbase));                      \
            ull A;                                                                      \
            A = pk2(a.x); acc[i][0] = ffma2(A, b0.x, acc[i][0]); acc[i][1] = ffma2(A, b0.y, acc[i][1]); \
            A = pk2(a.y); acc[i][0] = ffma2(A, b1.x, acc[i][0]); acc[i][1] = ffma2(A, b1.y, acc[i][1]); \
            A = pk2(a.z); acc[i][0] = ffma2(A, b2.x, acc[i][0]); acc[i][1] = ffma2(A, b2.y, acc[i][1]); \
            A = pk2(a.w); acc[i][0] = ffma2(A, b3.x, acc[i][0]); acc[i][1] = ffma2(A, b3.y, acc[i][1]); \
        }                                                                               \
    }

// ---------------------------------------------------------------------------
// K0: WkT transpose (one-shot, 64KB)
// ---------------------------------------------------------------------------
__global__ __launch_bounds__(256) void k0_transpose(const float* __restrict__ Wk)
{
    __shared__ float tile[32][33];
    const int bx = blockIdx.x & 3, by = blockIdx.x >> 2;
    const int x = threadIdx.x & 31, y = threadIdx.x >> 5;  // 32 x 8
#pragma unroll
    for (int i = 0; i < 32; i += 8)
        tile[y + i][x] = Wk[(by * 32 + y + i) * 128 + bx * 32 + x];
    __syncthreads();
#pragma unroll
    for (int i = 0; i < 32; i += 8)
        g_wkt[(bx * 32 + y + i) * 128 + by * 32 + x] = tile[x][y + i];
}

// ---------------------------------------------------------------------------
// K1: q = query@Wq + bq;  qkt[n,h,g] = scale * sum_d q[h,d] * WkT[h*32+d][g]
// 64 nodes/CTA, warp-private 8 rows. NO __syncthreads. Weights via LDG.
// ---------------------------------------------------------------------------
__global__ __launch_bounds__(256, 3) void k1_kernel(
    const float* __restrict__ query, const float* __restrict__ Wq,
    const float* __restrict__ bq)
{
    __shared__ float bufQ[64 * 132];

    const int t = threadIdx.x;
    const int n0 = blockIdx.x * 64;
    const int lane = t & 31, wg = t >> 5;
    const int c0 = 4 * lane, r0 = 8 * wg;
    float* myA = bufQ + r0 * 132;   // warp-private 8 rows

#pragma unroll
    for (int i = 0; i < 8; i++) {
        const int row = n0 + r0 + i;
        float4 v = (row < NODES) ? *(const float4*)(query + (size_t)row * 128 + c0)
                                 : make_float4(0.f, 0.f, 0.f, 0.f);
        *(float4*)(myA + i * 132 + c0) = v;
    }
    __syncwarp();

    ull acc[8][2];
#pragma unroll
    for (int i = 0; i < 8; i++) { acc[i][0] = 0ull; acc[i][1] = 0ull; }
#pragma unroll 4
    for (int k = 0; k < 128; k += 4) {
        GEMM_STEP_LDGB(myA, k, Wq, k, c0, acc);
    }
    __syncwarp();

    {
        float4 b4 = *(const float4*)(bq + c0);
#pragma unroll
        for (int i = 0; i < 8; i++) {
            float lo0, hi0, lo1, hi1;
            upk(acc[i][0], lo0, hi0); upk(acc[i][1], lo1, hi1);
            *(float4*)(myA + i * 132 + c0) =
                make_float4(lo0 + b4.x, hi0 + b4.y, lo1 + b4.z, hi1 + b4.w);
        }
    }
    __syncwarp();

    const float scale = 0.17677669529663688f;  // 1/sqrt(32)
#pragma unroll
    for (int h = 0; h < 4; h++) {
        ull a2[8][2];
#pragma unroll
        for (int i = 0; i < 8; i++) { a2[i][0] = 0ull; a2[i][1] = 0ull; }
#pragma unroll 4
        for (int d = 0; d < 32; d += 4) {
            GEMM_STEP_LDGB(myA, h * 32 + d, g_wkt, h * 32 + d, c0, a2);
        }
#pragma unroll
        for (int i = 0; i < 8; i++) {
            if (n0 + r0 + i < NODES) {
                float4 o;
                upk(a2[i][0], o.x, o.y); upk(a2[i][1], o.z, o.w);
                o.x *= scale; o.y *= scale; o.z *= scale; o.w *= scale;
                *(float4*)(g_qkt + (size_t)(n0 + r0 + i) * 512 + h * 128 + c0) = o;
            }
        }
    }
}

// ---------------------------------------------------------------------------
// K2: attention core. One warp per node. COALESCED score pass:
// chunks of 4 rows, 8 lanes per row (each LDG = 4 x 128B lines = 4 wavefronts),
// per-lane head-partials, 3-level shfl_xor reduces all 4 rows at once.
// mask_idx==0 -> fp32-exact uniform 1/32 attention, no key reads.
// ---------------------------------------------------------------------------
__global__ __launch_bounds__(256) void k2_kernel(
    const float* __restrict__ key, const float* __restrict__ value,
    const int* __restrict__ mask_idx)
{
    __shared__ float  sqk[8][4][128];
    __shared__ float4 sscore[8][32];
    __shared__ float4 sattn[8][32];

    const int w = threadIdx.x >> 5, l = threadIdx.x & 31;
    const int n = blockIdx.x * 8 + w;

    const int mi = mask_idx[n];
    const int L = (mi == 0) ? 32 : mi;

    if (mi == 0) {
        const float ua = 1.0f / 32.0f;
        sattn[w][l] = make_float4(ua, ua, ua, ua);
    } else {
        {
            const float4* qsrc = (const float4*)(g_qkt + (size_t)n * 512);
#pragma unroll
            for (int h = 0; h < 4; h++)
                *(float4*)&sqk[w][h][4 * l] = qsrc[h * 32 + l];
        }
        __syncwarp();

        // ---- coalesced score pass ----
        const int j = l & 7;      // feature slice (16 floats)
        const int r = l >> 3;     // row within chunk (0..3)
        const int nch = (L + 3) >> 2;
        for (int c = 0; c < nch; c++) {
            const int s = c * 4 + r;
            const bool act = s < L;
            const float* krow = key + ((size_t)s * NODES + n) * 128;
            float p0 = 0.f, p1 = 0.f, p2 = 0.f, p3 = 0.f;
#pragma unroll
            for (int it = 0; it < 4; it++) {
                float4 kv = make_float4(0.f, 0.f, 0.f, 0.f);
                if (act) kv = *(const float4*)(krow + it * 32 + 4 * j);
                float4 q0 = *(const float4*)&sqk[w][0][it * 32 + 4 * j];
                float4 q1 = *(const float4*)&sqk[w][1][it * 32 + 4 * j];
                float4 q2 = *(const float4*)&sqk[w][2][it * 32 + 4 * j];
                float4 q3 = *(const float4*)&sqk[w][3][it * 32 + 4 * j];
                p0 = fmaf(kv.x, q0.x, fmaf(kv.y, q0.y, fmaf(kv.z, q0.z, fmaf(kv.w, q0.w, p0))));
                p1 = fmaf(kv.x, q1.x, fmaf(kv.y, q1.y, fmaf(kv.z, q1.z, fmaf(kv.w, q1.w, p1))));
                p2 = fmaf(kv.x, q2.x, fmaf(kv.y, q2.y, fmaf(kv.z, q2.z, fmaf(kv.w, q2.w, p2))));
                p3 = fmaf(kv.x, q3.x, fmaf(kv.y, q3.y, fmaf(kv.z, q3.z, fmaf(kv.w, q3.w, p3))));
            }
            // reduce over the 8 feature-lanes (all 4 rows in parallel)
#pragma unroll
            for (int off = 1; off <= 4; off <<= 1) {
                p0 += __shfl_xor_sync(0xffffffffu, p0, off);
                p1 += __shfl_xor_sync(0xffffffffu, p1, off);
                p2 += __shfl_xor_sync(0xffffffffu, p2, off);
                p3 += __shfl_xor_sync(0xffffffffu, p3, off);
            }
            if (j == 0 && act) sscore[w][s] = make_float4(p0, p1, p2, p3);
        }
        __syncwarp();

        // ---- softmax over seq (lane = s) ----
        float sc[4] = {-INFINITY, -INFINITY, -INFINITY, -INFINITY};
        if (l < L) {
            float4 v = sscore[w][l];
            sc[0] = v.x; sc[1] = v.y; sc[2] = v.z; sc[3] = v.w;
        }
        float at[4];
#pragma unroll
        for (int h = 0; h < 4; h++) {
            float m = sc[h];
#pragma unroll
            for (int off = 16; off; off >>= 1)
                m = fmaxf(m, __shfl_xor_sync(0xffffffffu, m, off));
            float e = __expf(sc[h] - m);   // -inf -> 0 exactly for masked lanes
            float ssum = e;
#pragma unroll
            for (int off = 16; off; off >>= 1)
                ssum += __shfl_xor_sync(0xffffffffu, ssum, off);
            at[h] = e / ssum;
        }
        sattn[w][l] = make_float4(at[0], at[1], at[2], at[3]);
    }
    __syncwarp();

    // ---- value accumulation (coalesced) ----
    float u0[4] = {0,0,0,0}, u1[4] = {0,0,0,0}, u2[4] = {0,0,0,0}, u3[4] = {0,0,0,0};
    const float* vbase = value + (size_t)n * 128 + 4 * l;
    int s = 0;
    for (; s + 2 <= L; s += 2) {
        float4 a  = sattn[w][s];
        float4 a2 = sattn[w][s + 1];
        float4 v  = *(const float4*)(vbase + (size_t)s * (NODES * 128));
        float4 v2 = *(const float4*)(vbase + (size_t)(s + 1) * (NODES * 128));
        float vv[4]  = {v.x, v.y, v.z, v.w};
        float vv2[4] = {v2.x, v2.y, v2.z, v2.w};
#pragma unroll
        for (int jj = 0; jj < 4; jj++) {
            u0[jj] = fmaf(a.x, vv[jj], u0[jj]);  u0[jj] = fmaf(a2.x, vv2[jj], u0[jj]);
            u1[jj] = fmaf(a.y, vv[jj], u1[jj]);  u1[jj] = fmaf(a2.y, vv2[jj], u1[jj]);
            u2[jj] = fmaf(a.z, vv[jj], u2[jj]);  u2[jj] = fmaf(a2.z, vv2[jj], u2[jj]);
            u3[jj] = fmaf(a.w, vv[jj], u3[jj]);  u3[jj] = fmaf(a2.w, vv2[jj], u3[jj]);
        }
    }
    if (s < L) {
        float4 a = sattn[w][s];
        float4 v = *(const float4*)(vbase + (size_t)s * (NODES * 128));
        float vv[4] = {v.x, v.y, v.z, v.w};
#pragma unroll
        for (int jj = 0; jj < 4; jj++) {
            u0[jj] = fmaf(a.x, vv[jj], u0[jj]);
            u1[jj] = fmaf(a.y, vv[jj], u1[jj]);
            u2[jj] = fmaf(a.z, vv[jj], u2[jj]);
            u3[jj] = fmaf(a.w, vv[jj], u3[jj]);
        }
    }
    float* ub = g_u + (size_t)n * 512 + 4 * l;
    *(float4*)(ub +   0) = make_float4(u0[0], u0[1], u0[2], u0[3]);
    *(float4*)(ub + 128) = make_float4(u1[0], u1[1], u1[2], u1[3]);
    *(float4*)(ub + 256) = make_float4(u2[0], u2[1], u2[2], u2[3]);
    *(float4*)(ub + 384) = make_float4(u3[0], u3[1], u3[2], u3[3]);
}

// ---------------------------------------------------------------------------
// K3 (R13 version, measured 69.8us): wv = u@Wv(per-head) + bv; out = wv@Wo
// + bo; LN; + query. 64 nodes/CTA, warp-private rows, NO __syncthreads.
// ---------------------------------------------------------------------------
__global__ __launch_bounds__(256, 3) void k3_kernel(
    const float* __restrict__ Wv, const float* __restrict__ bv,
    const float* __restrict__ Wo, const float* __restrict__ bo,
    const float* __restrict__ gamma, const float* __restrict__ beta,
    const float* __restrict__ query, float* __restrict__ out)
{
    __shared__ float bufWV[64 * 132];

    const int t = threadIdx.x;
    const int n0 = blockIdx.x * 64;
    const int lane = t & 31, wg = t >> 5;
    const int c0 = 4 * lane, r0 = 8 * wg;
    const int hoff = (c0 >> 5) * 128;   // head slice offset in u row
    float* myWV = bufWV + r0 * 132;

    const float* uptr[8];
#pragma unroll
    for (int i = 0; i < 8; i++) {
        int row = n0 + r0 + i;
        if (row >= NODES) row = 0;
        uptr[i] = g_u + (size_t)row * 512 + hoff;
    }

    // ---- stage A: wv[r][c0..c0+3] = sum_f u[r][h,f] * Wv[f][c0..] ----
    ull acc[8][2];
#pragma unroll
    for (int i = 0; i < 8; i++) { acc[i][0] = 0ull; acc[i][1] = 0ull; }
#pragma unroll 4
    for (int f = 0; f < 128; f += 4) {
        ulonglong2 b0 = *(const ulonglong2*)(Wv + (f + 0) * 128 + c0);
        ulonglong2 b1 = *(const ulonglong2*)(Wv + (f + 1) * 128 + c0);
        ulonglong2 b2 = *(const ulonglong2*)(Wv + (f + 2) * 128 + c0);
        ulonglong2 b3 = *(const ulonglong2*)(Wv + (f + 3) * 128 + c0);
#pragma unroll
        for (int i = 0; i < 8; i++) {
            float4 a = *(const float4*)(uptr[i] + f);
            ull A;
            A = pk2(a.x); acc[i][0] = ffma2(A, b0.x, acc[i][0]); acc[i][1] = ffma2(A, b0.y, acc[i][1]);
            A = pk2(a.y); acc[i][0] = ffma2(A, b1.x, acc[i][0]); acc[i][1] = ffma2(A, b1.y, acc[i][1]);
            A = pk2(a.z); acc[i][0] = ffma2(A, b2.x, acc[i][0]); acc[i][1] = ffma2(A, b2.y, acc[i][1]);
            A = pk2(a.w); acc[i][0] = ffma2(A, b3.x, acc[i][0]); acc[i][1] = ffma2(A, b3.y, acc[i][1]);
        }
    }
    {
        float4 b4 = *(const float4*)(bv + c0);
#pragma unroll
        for (int i = 0; i < 8; i++) {
            float lo0, hi0, lo1, hi1;
            upk(acc[i][0], lo0, hi0); upk(acc[i][1], lo1, hi1);
            *(float4*)(myWV + i * 132 + c0) =
                make_float4(lo0 + b4.x, hi0 + b4.y, lo1 + b4.z, hi1 + b4.w);
        }
    }
    __syncwarp();

    // ---- stage B: out = wv @ Wo + bo (Wo via LDG), LN, residual ----
    ull acc2[8][2];
#pragma unroll
    for (int i = 0; i < 8; i++) { acc2[i][0] = 0ull; acc2[i][1] = 0ull; }
#pragma unroll 4
    for (int k = 0; k < 128; k += 4) {
        GEMM_STEP_LDGB(myWV, k, Wo, k, c0, acc2);
    }

    float4 bo4 = *(const float4*)(bo + c0);
    float4 g4  = *(const float4*)(gamma + c0);
    float4 be4 = *(const float4*)(beta + c0);

#pragma unroll
    for (int i = 0; i < 8; i++) {
        float o[4];
        upk(acc2[i][0], o[0], o[1]); upk(acc2[i][1], o[2], o[3]);
        o[0] += bo4.x; o[1] += bo4.y; o[2] += bo4.z; o[3] += bo4.w;
        float s  = o[0] + o[1] + o[2] + o[3];
        float sq = o[0]*o[0] + o[1]*o[1] + o[2]*o[2] + o[3]*o[3];
#pragma unroll
        for (int off = 16; off; off >>= 1) {
            s  += __shfl_xor_sync(0xffffffffu, s, off);
            sq += __shfl_xor_sync(0xffffffffu, sq, off);
        }
        const int row = n0 + r0 + i;
        if (row < NODES) {
            float mu = s * (1.f / 128.f);
            float var = sq * (1.f / 128.f) - mu * mu;
            float rstd = rsqrtf(var + 1e-5f);
            float4 q4 = *(const float4*)(query + (size_t)row * 128 + c0);
            float4 res;
            res.x = q4.x + (o[0] - mu) * rstd * g4.x + be4.x;
            res.y = q4.y + (o[1] - mu) * rstd * g4.y + be4.y;
            res.z = q4.z + (o[2] - mu) * rstd * g4.z + be4.z;
            res.w = q4.w + (o[3] - mu) * rstd * g4.w + be4.w;
            *(float4*)(out + (size_t)row * 128 + c0) = res;
        }
    }
}

extern "C" void kernel_launch(void* const* d_in, const int* in_sizes, int n_in,
                              void* d_out, int out_size) {
    const float* query = (const float*)d_in[0];
    const float* key   = (const float*)d_in[1];
    const float* value = (const float*)d_in[2];
    const int*   midx  = (const int*)d_in[3];
    const float* Wq = (const float*)d_in[4];
    const float* bq = (const float*)d_in[5];
    const float* Wk = (const float*)d_in[6];
    // bk = d_in[7] cancels in softmax (and is zero) — unused
    const float* Wv = (const float*)d_in[8];
    const float* bv = (const float*)d_in[9];
    const float* Wo = (const float*)d_in[10];
    const float* bo = (const float*)d_in[11];
    const float* gamma = (const float*)d_in[12];
    const float* beta  = (const float*)d_in[13];
    float* out = (float*)d_out;

    const int grid14 = (NODES + 63) / 64;  // 313
    k0_transpose<<<16, 256>>>(Wk);
    k1_kernel<<<grid14, 256>>>(query, Wq, bq);
    k2_kernel<<<NODES / 8, 256>>>(key, value, midx);
    k3_kernel<<<grid14, 256>>>(Wv, bv, Wo, bo, gamma, beta, query, out);
}

// round 16
// speedup vs baseline: 1.0952x; 1.0952x over previous
#include <cuda_runtime.h>
#include <math.h>

#define NODES 20000

typedef unsigned long long ull;

__device__ float g_qkt[(size_t)NODES * 512];
__device__ float g_u[(size_t)NODES * 512];
__device__ float g_wkt[128 * 128];   // WkT[c][g] = Wk[g][c]
__device__ int g_hist[32];
__device__ int g_start[32];
__device__ int g_perm[NODES];

__device__ __forceinline__ ull pk2(float x) {
    unsigned xi = __float_as_uint(x);
    ull r;
    asm("mov.b64 %0, {%1, %1};" : "=l"(r) : "r"(xi), "r"(xi));
    return r;
}
__device__ __forceinline__ ull ffma2(ull a, ull b, ull c) {
    ull d;
    asm("fma.rn.f32x2 %0, %1, %2, %3;" : "=l"(d) : "l"(a), "l"(b), "l"(c));
    return d;
}
__device__ __forceinline__ void upk(ull v, float& lo, float& hi) {
    unsigned a, b;
    asm("mov.b64 {%0, %1}, %2;" : "=r"(a), "=r"(b) : "l"(v));
    lo = __uint_as_float(a); hi = __uint_as_float(b);
}

// 8 rows x 4 cols over 4 k: A from smem (warp-private rows, broadcast reads),
// B via 16B-per-lane loads from gB (global, coalesced 512B rows, L1-hot).
#define GEMM_STEP_LDGB(bA, kbase, gB, kg, c0, acc)                                     \
    {                                                                                   \
        ulonglong2 b0 = *(const ulonglong2*)((gB) + ((kg) + 0) * 128 + (c0));           \
        ulonglong2 b1 = *(const ulonglong2*)((gB) + ((kg) + 1) * 128 + (c0));           \
        ulonglong2 b2 = *(const ulonglong2*)((gB) + ((kg) + 2) * 128 + (c0));           \
        ulonglong2 b3 = *(const ulonglong2*)((gB) + ((kg) + 3) * 128 + (c0));           \
        _Pragma("unroll")                                                               \
        for (int i = 0; i < 8; i++) {                                                   \
            float4 a = *(const float4*)((bA) + i * 132 + (kbase));                      \
            ull A;                                                                      \
            A = pk2(a.x); acc[i][0] = ffma2(A, b0.x, acc[i][0]); acc[i][1] = ffma2(A, b0.y, acc[i][1]); \
            A = pk2(a.y); acc[i][0] = ffma2(A, b1.x, acc[i][0]); acc[i][1] = ffma2(A, b1.y, acc[i][1]); \
            A = pk2(a.z); acc[i][0] = ffma2(A, b2.x, acc[i][0]); acc[i][1] = ffma2(A, b2.y, acc[i][1]); \
            A = pk2(a.w); acc[i][0] = ffma2(A, b3.x, acc[i][0]); acc[i][1] = ffma2(A, b3.y, acc[i][1]); \
        }                                                                               \
    }

// ---------------------------------------------------------------------------
// K0: WkT transpose (one-shot, 64KB)
// ---------------------------------------------------------------------------
__global__ __launch_bounds__(256) void k0_transpose(const float* __restrict__ Wk)
{
    __shared__ float tile[32][33];
    const int bx = blockIdx.x & 3, by = blockIdx.x >> 2;
    const int x = threadIdx.x & 31, y = threadIdx.x >> 5;  // 32 x 8
#pragma unroll
    for (int i = 0; i < 32; i += 8)
        tile[y + i][x] = Wk[(by * 32 + y + i) * 128 + bx * 32 + x];
    __syncthreads();
#pragma unroll
    for (int i = 0; i < 32; i += 8)
        g_wkt[(bx * 32 + y + i) * 128 + by * 32 + x] = tile[x][y + i];
}

// ---------------------------------------------------------------------------
// KH: counting sort of nodes by effective L (ragged-mask load balancing).
// Re-run every launch (graph replays) -> zero, hist, scan, scatter.
// ---------------------------------------------------------------------------
__global__ void kh_zero() {
    if (threadIdx.x < 32) g_hist[threadIdx.x] = 0;
}
__global__ __launch_bounds__(256) void kh_hist(const int* __restrict__ mask_idx) {
    const int n = blockIdx.x * 256 + threadIdx.x;
    if (n < NODES) {
        const int mi = mask_idx[n];
        const int L = (mi == 0) ? 32 : mi;
        atomicAdd(&g_hist[L - 1], 1);
    }
}
__global__ void kh_scan() {
    if (threadIdx.x == 0) {
        int acc = 0;
        for (int b = 0; b < 32; b++) { g_start[b] = acc; acc += g_hist[b]; }
    }
}
__global__ __launch_bounds__(256) void kh_scatter(const int* __restrict__ mask_idx) {
    const int n = blockIdx.x * 256 + threadIdx.x;
    if (n < NODES) {
        const int mi = mask_idx[n];
        const int L = (mi == 0) ? 32 : mi;
        const int pos = atomicAdd(&g_start[L - 1], 1);
        g_perm[pos] = n;
    }
}

// ---------------------------------------------------------------------------
// K1: q = query@Wq + bq;  qkt[n,h,g] = scale * sum_d q[h,d] * WkT[h*32+d][g]
// 64 nodes/CTA, warp-private 8 rows. NO __syncthreads. Weights via LDG.
// ---------------------------------------------------------------------------
__global__ __launch_bounds__(256, 3) void k1_kernel(
    const float* __restrict__ query, const float* __restrict__ Wq,
    const float* __restrict__ bq)
{
    __shared__ float bufQ[64 * 132];

    const int t = threadIdx.x;
    const int n0 = blockIdx.x * 64;
    const int lane = t & 31, wg = t >> 5;
    const int c0 = 4 * lane, r0 = 8 * wg;
    float* myA = bufQ + r0 * 132;   // warp-private 8 rows

#pragma unroll
    for (int i = 0; i < 8; i++) {
        const int row = n0 + r0 + i;
        float4 v = (row < NODES) ? *(const float4*)(query + (size_t)row * 128 + c0)
                                 : make_float4(0.f, 0.f, 0.f, 0.f);
        *(float4*)(myA + i * 132 + c0) = v;
    }
    __syncwarp();

    ull acc[8][2];
#pragma unroll
    for (int i = 0; i < 8; i++) { acc[i][0] = 0ull; acc[i][1] = 0ull; }
#pragma unroll 4
    for (int k = 0; k < 128; k += 4) {
        GEMM_STEP_LDGB(myA, k, Wq, k, c0, acc);
    }
    __syncwarp();

    {
        float4 b4 = *(const float4*)(bq + c0);
#pragma unroll
        for (int i = 0; i < 8; i++) {
            float lo0, hi0, lo1, hi1;
            upk(acc[i][0], lo0, hi0); upk(acc[i][1], lo1, hi1);
            *(float4*)(myA + i * 132 + c0) =
                make_float4(lo0 + b4.x, hi0 + b4.y, lo1 + b4.z, hi1 + b4.w);
        }
    }
    __syncwarp();

    const float scale = 0.17677669529663688f;  // 1/sqrt(32)
#pragma unroll
    for (int h = 0; h < 4; h++) {
        ull a2[8][2];
#pragma unroll
        for (int i = 0; i < 8; i++) { a2[i][0] = 0ull; a2[i][1] = 0ull; }
#pragma unroll 4
        for (int d = 0; d < 32; d += 4) {
            GEMM_STEP_LDGB(myA, h * 32 + d, g_wkt, h * 32 + d, c0, a2);
        }
#pragma unroll
        for (int i = 0; i < 8; i++) {
            if (n0 + r0 + i < NODES) {
                float4 o;
                upk(a2[i][0], o.x, o.y); upk(a2[i][1], o.z, o.w);
                o.x *= scale; o.y *= scale; o.z *= scale; o.w *= scale;
                *(float4*)(g_qkt + (size_t)(n0 + r0 + i) * 512 + h * 128 + c0) = o;
            }
        }
    }
}

// ---------------------------------------------------------------------------
// K2: attention core (R13/R14 measured version: lane-per-row score pass, deep
// MLP). One warp per node, node id from L-sorted permutation -> warps in a
// CTA have ~equal L (no straggler slots). Only rows s < L are read from HBM.
// mask_idx==0: reference's -1e9 on ALL positions annihilates score
// differences in fp32 -> softmax is exactly uniform 1/32. Skip key reads.
// ---------------------------------------------------------------------------
__global__ __launch_bounds__(256) void k2_kernel(
    const float* __restrict__ key, const float* __restrict__ value,
    const int* __restrict__ mask_idx)
{
    __shared__ float  sqk[8][4][128];
    __shared__ float4 sattn[8][32];

    const int w = threadIdx.x >> 5, l = threadIdx.x & 31;
    const int n = g_perm[blockIdx.x * 8 + w];

    const int mi = mask_idx[n];
    const int L = (mi == 0) ? 32 : mi;

    if (mi == 0) {
        const float ua = 1.0f / 32.0f;
        sattn[w][l] = make_float4(ua, ua, ua, ua);
    } else {
        {
            const float4* qsrc = (const float4*)(g_qkt + (size_t)n * 512);
#pragma unroll
            for (int h = 0; h < 4; h++)
                *(float4*)&sqk[w][h][4 * l] = qsrc[h * 32 + l];
        }
        __syncwarp();

        float sc[4] = {-INFINITY, -INFINITY, -INFINITY, -INFINITY};
        if (l < L) {
            const float4* krow = (const float4*)(key + ((size_t)l * NODES + n) * 128);
            float s0 = 0.f, s1 = 0.f, s2 = 0.f, s3 = 0.f;
#pragma unroll 4
            for (int c = 0; c < 32; c++) {
                float4 kv = krow[c];
                float4 q0 = *(const float4*)&sqk[w][0][4 * c];
                float4 q1 = *(const float4*)&sqk[w][1][4 * c];
                float4 q2 = *(const float4*)&sqk[w][2][4 * c];
                float4 q3 = *(const float4*)&sqk[w][3][4 * c];
                s0 = fmaf(kv.x, q0.x, fmaf(kv.y, q0.y, fmaf(kv.z, q0.z, fmaf(kv.w, q0.w, s0))));
                s1 = fmaf(kv.x, q1.x, fmaf(kv.y, q1.y, fmaf(kv.z, q1.z, fmaf(kv.w, q1.w, s1))));
                s2 = fmaf(kv.x, q2.x, fmaf(kv.y, q2.y, fmaf(kv.z, q2.z, fmaf(kv.w, q2.w, s2))));
                s3 = fmaf(kv.x, q3.x, fmaf(kv.y, q3.y, fmaf(kv.z, q3.z, fmaf(kv.w, q3.w, s3))));
            }
            sc[0] = s0; sc[1] = s1; sc[2] = s2; sc[3] = s3;
        }

        float at[4];
#pragma unroll
        for (int h = 0; h < 4; h++) {
            float m = sc[h];
#pragma unroll
            for (int off = 16; off; off >>= 1)
                m = fmaxf(m, __shfl_xor_sync(0xffffffffu, m, off));
            float e = __expf(sc[h] - m);   // -inf -> 0 exactly for masked lanes
            float ssum = e;
#pragma unroll
            for (int off = 16; off; off >>= 1)
                ssum += __shfl_xor_sync(0xffffffffu, ssum, off);
            at[h] = e / ssum;
        }
        sattn[w][l] = make_float4(at[0], at[1], at[2], at[3]);
    }
    __syncwarp();

    float u0[4] = {0,0,0,0}, u1[4] = {0,0,0,0}, u2[4] = {0,0,0,0}, u3[4] = {0,0,0,0};
    const float* vbase = value + (size_t)n * 128 + 4 * l;
    int s = 0;
    for (; s + 2 <= L; s += 2) {
        float4 a  = sattn[w][s];
        float4 a2 = sattn[w][s + 1];
        float4 v  = *(const float4*)(vbase + (size_t)s * (NODES * 128));
        float4 v2 = *(const float4*)(vbase + (size_t)(s + 1) * (NODES * 128));
        float vv[4]  = {v.x, v.y, v.z, v.w};
        float vv2[4] = {v2.x, v2.y, v2.z, v2.w};
#pragma unroll
        for (int jj = 0; jj < 4; jj++) {
            u0[jj] = fmaf(a.x, vv[jj], u0[jj]);  u0[jj] = fmaf(a2.x, vv2[jj], u0[jj]);
            u1[jj] = fmaf(a.y, vv[jj], u1[jj]);  u1[jj] = fmaf(a2.y, vv2[jj], u1[jj]);
            u2[jj] = fmaf(a.z, vv[jj], u2[jj]);  u2[jj] = fmaf(a2.z, vv2[jj], u2[jj]);
            u3[jj] = fmaf(a.w, vv[jj], u3[jj]);  u3[jj] = fmaf(a2.w, vv2[jj], u3[jj]);
        }
    }
    if (s < L) {
        float4 a = sattn[w][s];
        float4 v = *(const float4*)(vbase + (size_t)s * (NODES * 128));
        float vv[4] = {v.x, v.y, v.z, v.w};
#pragma unroll
        for (int jj = 0; jj < 4; jj++) {
            u0[jj] = fmaf(a.x, vv[jj], u0[jj]);
            u1[jj] = fmaf(a.y, vv[jj], u1[jj]);
            u2[jj] = fmaf(a.z, vv[jj], u2[jj]);
            u3[jj] = fmaf(a.w, vv[jj], u3[jj]);
        }
    }
    float* ub = g_u + (size_t)n * 512 + 4 * l;
    *(float4*)(ub +   0) = make_float4(u0[0], u0[1], u0[2], u0[3]);
    *(float4*)(ub + 128) = make_float4(u1[0], u1[1], u1[2], u1[3]);
    *(float4*)(ub + 256) = make_float4(u2[0], u2[1], u2[2], u2[3]);
    *(float4*)(ub + 384) = make_float4(u3[0], u3[1], u3[2], u3[3]);
}

// ---------------------------------------------------------------------------
// K3 (R13 version, measured 69.8us): wv = u@Wv(per-head) + bv; out = wv@Wo
// + bo; LN; + query. 64 nodes/CTA, warp-private rows, NO __syncthreads.
// ---------------------------------------------------------------------------
__global__ __launch_bounds__(256, 3) void k3_kernel(
    const float* __restrict__ Wv, const float* __restrict__ bv,
    const float* __restrict__ Wo, const float* __restrict__ bo,
    const float* __restrict__ gamma, const float* __restrict__ beta,
    const float* __restrict__ query, float* __restrict__ out)
{
    __shared__ float bufWV[64 * 132];

    const int t = threadIdx.x;
    const int n0 = blockIdx.x * 64;
    const int lane = t & 31, wg = t >> 5;
    const int c0 = 4 * lane, r0 = 8 * wg;
    const int hoff = (c0 >> 5) * 128;   // head slice offset in u row
    float* myWV = bufWV + r0 * 132;

    const float* uptr[8];
#pragma unroll
    for (int i = 0; i < 8; i++) {
        int row = n0 + r0 + i;
        if (row >= NODES) row = 0;
        uptr[i] = g_u + (size_t)row * 512 + hoff;
    }

    // ---- stage A: wv[r][c0..c0+3] = sum_f u[r][h,f] * Wv[f][c0..] ----
    ull acc[8][2];
#pragma unroll
    for (int i = 0; i < 8; i++) { acc[i][0] = 0ull; acc[i][1] = 0ull; }
#pragma unroll 4
    for (int f = 0; f < 128; f += 4) {
        ulonglong2 b0 = *(const ulonglong2*)(Wv + (f + 0) * 128 + c0);
        ulonglong2 b1 = *(const ulonglong2*)(Wv + (f + 1) * 128 + c0);
        ulonglong2 b2 = *(const ulonglong2*)(Wv + (f + 2) * 128 + c0);
        ulonglong2 b3 = *(const ulonglong2*)(Wv + (f + 3) * 128 + c0);
#pragma unroll
        for (int i = 0; i < 8; i++) {
            float4 a = *(const float4*)(uptr[i] + f);
            ull A;
            A = pk2(a.x); acc[i][0] = ffma2(A, b0.x, acc[i][0]); acc[i][1] = ffma2(A, b0.y, acc[i][1]);
            A = pk2(a.y); acc[i][0] = ffma2(A, b1.x, acc[i][0]); acc[i][1] = ffma2(A, b1.y, acc[i][1]);
            A = pk2(a.z); acc[i][0] = ffma2(A, b2.x, acc[i][0]); acc[i][1] = ffma2(A, b2.y, acc[i][1]);
            A = pk2(a.w); acc[i][0] = ffma2(A, b3.x, acc[i][0]); acc[i][1] = ffma2(A, b3.y, acc[i][1]);
        }
    }
    {
        float4 b4 = *(const float4*)(bv + c0);
#pragma unroll
        for (int i = 0; i < 8; i++) {
            float lo0, hi0, lo1, hi1;
            upk(acc[i][0], lo0, hi0); upk(acc[i][1], lo1, hi1);
            *(float4*)(myWV + i * 132 + c0) =
                make_float4(lo0 + b4.x, hi0 + b4.y, lo1 + b4.z, hi1 + b4.w);
        }
    }
    __syncwarp();

    // ---- stage B: out = wv @ Wo + bo (Wo via LDG), LN, residual ----
    ull acc2[8][2];
#pragma unroll
    for (int i = 0; i < 8; i++) { acc2[i][0] = 0ull; acc2[i][1] = 0ull; }
#pragma unroll 4
    for (int k = 0; k < 128; k += 4) {
        GEMM_STEP_LDGB(myWV, k, Wo, k, c0, acc2);
    }

    float4 bo4 = *(const float4*)(bo + c0);
    float4 g4  = *(const float4*)(gamma + c0);
    float4 be4 = *(const float4*)(beta + c0);

#pragma unroll
    for (int i = 0; i < 8; i++) {
        float o[4];
        upk(acc2[i][0], o[0], o[1]); upk(acc2[i][1], o[2], o[3]);
        o[0] += bo4.x; o[1] += bo4.y; o[2] += bo4.z; o[3] += bo4.w;
        float s  = o[0] + o[1] + o[2] + o[3];
        float sq = o[0]*o[0] + o[1]*o[1] + o[2]*o[2] + o[3]*o[3];
#pragma unroll
        for (int off = 16; off; off >>= 1) {
            s  += __shfl_xor_sync(0xffffffffu, s, off);
            sq += __shfl_xor_sync(0xffffffffu, sq, off);
        }
        const int row = n0 + r0 + i;
        if (row < NODES) {
            float mu = s * (1.f / 128.f);
            float var = sq * (1.f / 128.f) - mu * mu;
            float rstd = rsqrtf(var + 1e-5f);
            float4 q4 = *(const float4*)(query + (size_t)row * 128 + c0);
            float4 res;
            res.x = q4.x + (o[0] - mu) * rstd * g4.x + be4.x;
            res.y = q4.y + (o[1] - mu) * rstd * g4.y + be4.y;
            res.z = q4.z + (o[2] - mu) * rstd * g4.z + be4.z;
            res.w = q4.w + (o[3] - mu) * rstd * g4.w + be4.w;
            *(float4*)(out + (size_t)row * 128 + c0) = res;
        }
    }
}

extern "C" void kernel_launch(void* const* d_in, const int* in_sizes, int n_in,
                              void* d_out, int out_size) {
    const float* query = (const float*)d_in[0];
    const float* key   = (const float*)d_in[1];
    const float* value = (const float*)d_in[2];
    const int*   midx  = (const int*)d_in[3];
    const float* Wq = (const float*)d_in[4];
    const float* bq = (const float*)d_in[5];
    const float* Wk = (const float*)d_in[6];
    // bk = d_in[7] cancels in softmax (and is zero) — unused
    const float* Wv = (const float*)d_in[8];
    const float* bv = (const float*)d_in[9];
    const float* Wo = (const float*)d_in[10];
    const float* bo = (const float*)d_in[11];
    const float* gamma = (const float*)d_in[12];
    const float* beta  = (const float*)d_in[13];
    float* out = (float*)d_out;

    const int grid14 = (NODES + 63) / 64;  // 313
    const int gridN  = (NODES + 255) / 256;

    k0_transpose<<<16, 256>>>(Wk);
    kh_zero<<<1, 32>>>();
    kh_hist<<<gridN, 256>>>(midx);
    kh_scan<<<1, 32>>>();
    kh_scatter<<<gridN, 256>>>(midx);
    k1_kernel<<<grid14, 256>>>(query, Wq, bq);
    k2_kernel<<<NODES / 8, 256>>>(key, value, midx);
    k3_kernel<<<grid14, 256>>>(Wv, bv, Wo, bo, gamma, beta, query, out);
}

// round 17
// speedup vs baseline: 1.1911x; 1.0876x over previous
#include <cuda_runtime.h>
#include <math.h>

#define NODES 20000

typedef unsigned long long ull;

__device__ float g_qkt[(size_t)NODES * 512];
__device__ float g_u[(size_t)NODES * 512];
__device__ float g_wkt[128 * 128];   // WkT[c][g] = Wk[g][c]

__device__ __forceinline__ ull pk2(float x) {
    unsigned xi = __float_as_uint(x);
    ull r;
    asm("mov.b64 %0, {%1, %1};" : "=l"(r) : "r"(xi), "r"(xi));
    return r;
}
__device__ __forceinline__ ull ffma2(ull a, ull b, ull c) {
    ull d;
    asm("fma.rn.f32x2 %0, %1, %2, %3;" : "=l"(d) : "l"(a), "l"(b), "l"(c));
    return d;
}
__device__ __forceinline__ void upk(ull v, float& lo, float& hi) {
    unsigned a, b;
    asm("mov.b64 {%0, %1}, %2;" : "=r"(a), "=r"(b) : "l"(v));
    lo = __uint_as_float(a); hi = __uint_as_float(b);
}

// 8 rows x 4 cols over 4 k: A from smem (warp-private rows, broadcast reads),
// B via 16B-per-lane loads from gB (global, coalesced 512B rows, L1-hot).
#define GEMM_STEP_LDGB(bA, kbase, gB, kg, c0, acc)                                     \
    {                                                                                   \
        ulonglong2 b0 = *(const ulonglong2*)((gB) + ((kg) + 0) * 128 + (c0));           \
        ulonglong2 b1 = *(const ulonglong2*)((gB) + ((kg) + 1) * 128 + (c0));           \
        ulonglong2 b2 = *(const ulonglong2*)((gB) + ((kg) + 2) * 128 + (c0));           \
        ulonglong2 b3 = *(const ulonglong2*)((gB) + ((kg) + 3) * 128 + (c0));           \
        _Pragma("unroll")                                                               \
        for (int i = 0; i < 8; i++) {                                                   \
            float4 a = *(const float4*)((bA) + i * 132 + (kbase));                      \
            ull A;                                                                      \
            A = pk2(a.x); acc[i][0] = ffma2(A, b0.x, acc[i][0]); acc[i][1] = ffma2(A, b0.y, acc[i][1]); \
            A = pk2(a.y); acc[i][0] = ffma2(A, b1.x, acc[i][0]); acc[i][1] = ffma2(A, b1.y, acc[i][1]); \
            A = pk2(a.z); acc[i][0] = ffma2(A, b2.x, acc[i][0]); acc[i][1] = ffma2(A, b2.y, acc[i][1]); \
            A = pk2(a.w); acc[i][0] = ffma2(A, b3.x, acc[i][0]); acc[i][1] = ffma2(A, b3.y, acc[i][1]); \
        }                                                                               \
    }

// ---------------------------------------------------------------------------
// K0: WkT transpose (one-shot, 64KB)
// ---------------------------------------------------------------------------
__global__ __launch_bounds__(256) void k0_transpose(const float* __restrict__ Wk)
{
    __shared__ float tile[32][33];
    const int bx = blockIdx.x & 3, by = blockIdx.x >> 2;
    const int x = threadIdx.x & 31, y = threadIdx.x >> 5;  // 32 x 8
#pragma unroll
    for (int i = 0; i < 32; i += 8)
        tile[y + i][x] = Wk[(by * 32 + y + i) * 128 + bx * 32 + x];
    __syncthreads();
#pragma unroll
    for (int i = 0; i < 32; i += 8)
        g_wkt[(bx * 32 + y + i) * 128 + by * 32 + x] = tile[x][y + i];
}

// ---------------------------------------------------------------------------
// FUSED kernel: each warp carries its 8 nodes through all three phases.
//   Phase 1 (k1): q = query@Wq + bq; qkt = scale * q @ WkT  -> g_qkt
//   Phase 2 (k2): per node: scores (lane-per-row, deep MLP), softmax,
//                 value accumulation -> g_u.  mask_idx==0 -> exact uniform
//                 1/32 attention (fp32 -1e9 saturation), no key reads.
//   Phase 3 (k3): wv = u@Wv + bv; out = wv@Wo + bo; LN; + query
// All dependencies are warp-local (same-lane or __syncwarp-ordered).
// NO __syncthreads anywhere. Phase-2 scratch aliases the warp's tile slice.
// ---------------------------------------------------------------------------
__global__ __launch_bounds__(256, 3) void fused_kernel(
    const float* __restrict__ query, const float* __restrict__ Wq,
    const float* __restrict__ bq,
    const float* __restrict__ key, const float* __restrict__ value,
    const int* __restrict__ mask_idx,
    const float* __restrict__ Wv, const float* __restrict__ bv,
    const float* __restrict__ Wo, const float* __restrict__ bo,
    const float* __restrict__ gamma, const float* __restrict__ beta,
    float* __restrict__ out)
{
    __shared__ float bufA[64 * 132];   // 33.8KB: phase1 A/Q, phase2 scratch, phase3 wv

    const int t = threadIdx.x;
    const int n0 = blockIdx.x * 64;
    const int lane = t & 31, wg = t >> 5;
    const int c0 = 4 * lane, r0 = 8 * wg;
    float* myA = bufA + r0 * 132;      // warp-private 8-row slice (1056 floats)

    // ================= Phase 1: projections =================
#pragma unroll
    for (int i = 0; i < 8; i++) {
        const int row = n0 + r0 + i;
        float4 v = (row < NODES) ? *(const float4*)(query + (size_t)row * 128 + c0)
                                 : make_float4(0.f, 0.f, 0.f, 0.f);
        *(float4*)(myA + i * 132 + c0) = v;
    }
    __syncwarp();

    {
        ull acc[8][2];
#pragma unroll
        for (int i = 0; i < 8; i++) { acc[i][0] = 0ull; acc[i][1] = 0ull; }
#pragma unroll 4
        for (int k = 0; k < 128; k += 4) {
            GEMM_STEP_LDGB(myA, k, Wq, k, c0, acc);
        }
        __syncwarp();
        float4 b4 = *(const float4*)(bq + c0);
#pragma unroll
        for (int i = 0; i < 8; i++) {
            float lo0, hi0, lo1, hi1;
            upk(acc[i][0], lo0, hi0); upk(acc[i][1], lo1, hi1);
            *(float4*)(myA + i * 132 + c0) =
                make_float4(lo0 + b4.x, hi0 + b4.y, lo1 + b4.z, hi1 + b4.w);
        }
        __syncwarp();
    }

    const float scale = 0.17677669529663688f;  // 1/sqrt(32)
#pragma unroll
    for (int h = 0; h < 4; h++) {
        ull a2[8][2];
#pragma unroll
        for (int i = 0; i < 8; i++) { a2[i][0] = 0ull; a2[i][1] = 0ull; }
#pragma unroll 4
        for (int d = 0; d < 32; d += 4) {
            GEMM_STEP_LDGB(myA, h * 32 + d, g_wkt, h * 32 + d, c0, a2);
        }
#pragma unroll
        for (int i = 0; i < 8; i++) {
            if (n0 + r0 + i < NODES) {
                float4 o;
                upk(a2[i][0], o.x, o.y); upk(a2[i][1], o.z, o.w);
                o.x *= scale; o.y *= scale; o.z *= scale; o.w *= scale;
                *(float4*)(g_qkt + (size_t)(n0 + r0 + i) * 512 + h * 128 + c0) = o;
            }
        }
    }
    __syncwarp();   // Q tile dead; warp-local scratch reuse begins

    // ================= Phase 2: attention (8 nodes sequentially) =================
    {
        float*  sqk   = myA;                         // 512 floats
        float4* sattn = (float4*)(myA + 512);        // 32 float4 (16B-aligned)

        for (int i = 0; i < 8; i++) {
            const int n = n0 + r0 + i;
            if (n >= NODES) break;
            const int mi = mask_idx[n];
            const int L = (mi == 0) ? 32 : mi;

            if (mi == 0) {
                const float ua = 1.0f / 32.0f;
                sattn[lane] = make_float4(ua, ua, ua, ua);
            } else {
                {
                    const float4* qsrc = (const float4*)(g_qkt + (size_t)n * 512);
#pragma unroll
                    for (int h = 0; h < 4; h++)
                        *(float4*)(sqk + h * 128 + 4 * lane) = qsrc[h * 32 + lane];
                }
                __syncwarp();

                float sc[4] = {-INFINITY, -INFINITY, -INFINITY, -INFINITY};
                if (lane < L) {
                    const float4* krow = (const float4*)(key + ((size_t)lane * NODES + n) * 128);
                    float s0 = 0.f, s1 = 0.f, s2 = 0.f, s3 = 0.f;
#pragma unroll 4
                    for (int c = 0; c < 32; c++) {
                        float4 kv = krow[c];
                        float4 q0 = *(const float4*)(sqk + 0 * 128 + 4 * c);
                        float4 q1 = *(const float4*)(sqk + 1 * 128 + 4 * c);
                        float4 q2 = *(const float4*)(sqk + 2 * 128 + 4 * c);
                        float4 q3 = *(const float4*)(sqk + 3 * 128 + 4 * c);
                        s0 = fmaf(kv.x, q0.x, fmaf(kv.y, q0.y, fmaf(kv.z, q0.z, fmaf(kv.w, q0.w, s0))));
                        s1 = fmaf(kv.x, q1.x, fmaf(kv.y, q1.y, fmaf(kv.z, q1.z, fmaf(kv.w, q1.w, s1))));
                        s2 = fmaf(kv.x, q2.x, fmaf(kv.y, q2.y, fmaf(kv.z, q2.z, fmaf(kv.w, q2.w, s2))));
                        s3 = fmaf(kv.x, q3.x, fmaf(kv.y, q3.y, fmaf(kv.z, q3.z, fmaf(kv.w, q3.w, s3))));
                    }
                    sc[0] = s0; sc[1] = s1; sc[2] = s2; sc[3] = s3;
                }

                float at[4];
#pragma unroll
                for (int h = 0; h < 4; h++) {
                    float m = sc[h];
#pragma unroll
                    for (int off = 16; off; off >>= 1)
                        m = fmaxf(m, __shfl_xor_sync(0xffffffffu, m, off));
                    float e = __expf(sc[h] - m);   // -inf -> 0 exactly for masked lanes
                    float ssum = e;
#pragma unroll
                    for (int off = 16; off; off >>= 1)
                        ssum += __shfl_xor_sync(0xffffffffu, ssum, off);
                    at[h] = e / ssum;
                }
                __syncwarp();   // sqk reads done before sattn write aliases usage
                sattn[lane] = make_float4(at[0], at[1], at[2], at[3]);
            }
            __syncwarp();

            float u0[4] = {0,0,0,0}, u1[4] = {0,0,0,0}, u2[4] = {0,0,0,0}, u3[4] = {0,0,0,0};
            const float* vbase = value + (size_t)n * 128 + 4 * lane;
            int s = 0;
            for (; s + 2 <= L; s += 2) {
                float4 a  = sattn[s];
                float4 a2 = sattn[s + 1];
                float4 v  = *(const float4*)(vbase + (size_t)s * (NODES * 128));
                float4 v2 = *(const float4*)(vbase + (size_t)(s + 1) * (NODES * 128));
                float vv[4]  = {v.x, v.y, v.z, v.w};
                float vv2[4] = {v2.x, v2.y, v2.z, v2.w};
#pragma unroll
                for (int jj = 0; jj < 4; jj++) {
                    u0[jj] = fmaf(a.x, vv[jj], u0[jj]);  u0[jj] = fmaf(a2.x, vv2[jj], u0[jj]);
                    u1[jj] = fmaf(a.y, vv[jj], u1[jj]);  u1[jj] = fmaf(a2.y, vv2[jj], u1[jj]);
                    u2[jj] = fmaf(a.z, vv[jj], u2[jj]);  u2[jj] = fmaf(a2.z, vv2[jj], u2[jj]);
                    u3[jj] = fmaf(a.w, vv[jj], u3[jj]);  u3[jj] = fmaf(a2.w, vv2[jj], u3[jj]);
                }
            }
            if (s < L) {
                float4 a = sattn[s];
                float4 v = *(const float4*)(vbase + (size_t)s * (NODES * 128));
                float vv[4] = {v.x, v.y, v.z, v.w};
#pragma unroll
                for (int jj = 0; jj < 4; jj++) {
                    u0[jj] = fmaf(a.x, vv[jj], u0[jj]);
                    u1[jj] = fmaf(a.y, vv[jj], u1[jj]);
                    u2[jj] = fmaf(a.z, vv[jj], u2[jj]);
                    u3[jj] = fmaf(a.w, vv[jj], u3[jj]);
                }
            }
            float* ub = g_u + (size_t)n * 512 + 4 * lane;
            *(float4*)(ub +   0) = make_float4(u0[0], u0[1], u0[2], u0[3]);
            *(float4*)(ub + 128) = make_float4(u1[0], u1[1], u1[2], u1[3]);
            *(float4*)(ub + 256) = make_float4(u2[0], u2[1], u2[2], u2[3]);
            *(float4*)(ub + 384) = make_float4(u3[0], u3[1], u3[2], u3[3]);
            __syncwarp();   // scratch reuse + next-iter writes ordered
        }
    }
    __syncwarp();   // g_u writes visible warp-wide before cross-lane reads

    // ================= Phase 3: output projection + LN + residual =================
    {
        const int hoff = (c0 >> 5) * 128;   // head slice offset in u row
        float* myWV = myA;                  // aliases dead phase-1/2 scratch

        const float* uptr[8];
#pragma unroll
        for (int i = 0; i < 8; i++) {
            int row = n0 + r0 + i;
            if (row >= NODES) row = n0;     // clamp inside own CTA range (written data)
            uptr[i] = g_u + (size_t)row * 512 + hoff;
        }

        // stage A: wv[r][c0..c0+3] = sum_f u[r][h,f] * Wv[f][c0..]
        ull acc[8][2];
#pragma unroll
        for (int i = 0; i < 8; i++) { acc[i][0] = 0ull; acc[i][1] = 0ull; }
#pragma unroll 4
        for (int f = 0; f < 128; f += 4) {
            ulonglong2 b0 = *(const ulonglong2*)(Wv + (f + 0) * 128 + c0);
            ulonglong2 b1 = *(const ulonglong2*)(Wv + (f + 1) * 128 + c0);
            ulonglong2 b2 = *(const ulonglong2*)(Wv + (f + 2) * 128 + c0);
            ulonglong2 b3 = *(const ulonglong2*)(Wv + (f + 3) * 128 + c0);
#pragma unroll
            for (int i = 0; i < 8; i++) {
                float4 a = *(const float4*)(uptr[i] + f);
                ull A;
                A = pk2(a.x); acc[i][0] = ffma2(A, b0.x, acc[i][0]); acc[i][1] = ffma2(A, b0.y, acc[i][1]);
                A = pk2(a.y); acc[i][0] = ffma2(A, b1.x, acc[i][0]); acc[i][1] = ffma2(A, b1.y, acc[i][1]);
                A = pk2(a.z); acc[i][0] = ffma2(A, b2.x, acc[i][0]); acc[i][1] = ffma2(A, b2.y, acc[i][1]);
                A = pk2(a.w); acc[i][0] = ffma2(A, b3.x, acc[i][0]); acc[i][1] = ffma2(A, b3.y, acc[i][1]);
            }
        }
        {
            float4 b4 = *(const float4*)(bv + c0);
#pragma unroll
            for (int i = 0; i < 8; i++) {
                float lo0, hi0, lo1, hi1;
                upk(acc[i][0], lo0, hi0); upk(acc[i][1], lo1, hi1);
                *(float4*)(myWV + i * 132 + c0) =
                    make_float4(lo0 + b4.x, hi0 + b4.y, lo1 + b4.z, hi1 + b4.w);
            }
        }
        __syncwarp();

        // stage B: out = wv @ Wo + bo, LN, residual
        ull acc2[8][2];
#pragma unroll
        for (int i = 0; i < 8; i++) { acc2[i][0] = 0ull; acc2[i][1] = 0ull; }
#pragma unroll 4
        for (int k = 0; k < 128; k += 4) {
            GEMM_STEP_LDGB(myWV, k, Wo, k, c0, acc2);
        }

        float4 bo4 = *(const float4*)(bo + c0);
        float4 g4  = *(const float4*)(gamma + c0);
        float4 be4 = *(const float4*)(beta + c0);

#pragma unroll
        for (int i = 0; i < 8; i++) {
            float o[4];
            upk(acc2[i][0], o[0], o[1]); upk(acc2[i][1], o[2], o[3]);
            o[0] += bo4.x; o[1] += bo4.y; o[2] += bo4.z; o[3] += bo4.w;
            float s  = o[0] + o[1] + o[2] + o[3];
            float sq = o[0]*o[0] + o[1]*o[1] + o[2]*o[2] + o[3]*o[3];
#pragma unroll
            for (int off = 16; off; off >>= 1) {
                s  += __shfl_xor_sync(0xffffffffu, s, off);
                sq += __shfl_xor_sync(0xffffffffu, sq, off);
            }
            const int row = n0 + r0 + i;
            if (row < NODES) {
                float mu = s * (1.f / 128.f);
                float var = sq * (1.f / 128.f) - mu * mu;
                float rstd = rsqrtf(var + 1e-5f);
                float4 q4 = *(const float4*)(query + (size_t)row * 128 + c0);
                float4 res;
                res.x = q4.x + (o[0] - mu) * rstd * g4.x + be4.x;
                res.y = q4.y + (o[1] - mu) * rstd * g4.y + be4.y;
                res.z = q4.z + (o[2] - mu) * rstd * g4.z + be4.z;
                res.w = q4.w + (o[3] - mu) * rstd * g4.w + be4.w;
                *(float4*)(out + (size_t)row * 128 + c0) = res;
            }
        }
    }
}

extern "C" void kernel_launch(void* const* d_in, const int* in_sizes, int n_in,
                              void* d_out, int out_size) {
    const float* query = (const float*)d_in[0];
    const float* key   = (const float*)d_in[1];
    const float* value = (const float*)d_in[2];
    const int*   midx  = (const int*)d_in[3];
    const float* Wq = (const float*)d_in[4];
    const float* bq = (const float*)d_in[5];
    const float* Wk = (const float*)d_in[6];
    // bk = d_in[7] cancels in softmax (and is zero) — unused
    const float* Wv = (const float*)d_in[8];
    const float* bv = (const float*)d_in[9];
    const float* Wo = (const float*)d_in[10];
    const float* bo = (const float*)d_in[11];
    const float* gamma = (const float*)d_in[12];
    const float* beta  = (const float*)d_in[13];
    float* out = (float*)d_out;

    const int grid = (NODES + 63) / 64;  // 313
    k0_transpose<<<16, 256>>>(Wk);
    fused_kernel<<<grid, 256>>>(query, Wq, bq, key, value, midx,
                                Wv, bv, Wo, bo, gamma, beta, out);
}